// round 1
// baseline (speedup 1.0000x reference)
#include <cuda_runtime.h>
#include <math.h>

// Problem constants
#define NB  32
#define C   150
#define H   56
#define W   56
#define HW  (H*W)          // 3136
#define O   225
#define D   1350           // C*9
#define SPLIT 75

// Scratch (no cudaMalloc allowed)
__device__ float g_p2[O];
__device__ float g_s [NB*HW];   // per-pixel channel-weighted sum of x^2
__device__ float g_x2[NB*HW];   // 3x3 box sum of g_s

// ---------------------------------------------------------------------------
// Kernel A: p2[o] = sum_d wfull[d] * weight[o,d]^2   (wfull = 0.25 for d<675 else 0.75)
// ---------------------------------------------------------------------------
__global__ void p2_kernel(const float* __restrict__ wt) {
    int o = blockIdx.x;
    int t = threadIdx.x;
    float s = 0.f;
    for (int d = t; d < D; d += 256) {
        float v = wt[o * D + d];
        float wc = (d < SPLIT * 9) ? 0.25f : 0.75f;
        s += wc * v * v;
    }
    // warp reduce
    #pragma unroll
    for (int off = 16; off > 0; off >>= 1)
        s += __shfl_down_sync(0xffffffffu, s, off);
    __shared__ float red[8];
    if ((t & 31) == 0) red[t >> 5] = s;
    __syncthreads();
    if (t == 0) {
        float tot = 0.f;
        #pragma unroll
        for (int i = 0; i < 8; i++) tot += red[i];
        g_p2[o] = tot;
    }
}

// ---------------------------------------------------------------------------
// Kernel B1: s[n,hw] = sum_c wc * x[n,c,hw]^2
// ---------------------------------------------------------------------------
__global__ void chansum_kernel(const float* __restrict__ x) {
    int i = blockIdx.x * 256 + threadIdx.x;
    if (i >= NB * HW) return;
    int n = i / HW, hw = i % HW;
    const float* p = x + (size_t)n * C * HW + hw;
    float s = 0.f;
    #pragma unroll 5
    for (int c = 0; c < C; c++) {
        float v = p[(size_t)c * HW];
        float wc = (c < SPLIT) ? 0.25f : 0.75f;
        s += wc * v * v;
    }
    g_s[i] = s;
}

// ---------------------------------------------------------------------------
// Kernel B2: x2[n,h,w] = 3x3 zero-padded box sum of s
// ---------------------------------------------------------------------------
__global__ void box_kernel() {
    int i = blockIdx.x * 256 + threadIdx.x;
    if (i >= NB * HW) return;
    int n = i / HW, hw = i % HW;
    int h = hw / W, w = hw % W;
    float s = 0.f;
    #pragma unroll
    for (int dh = -1; dh <= 1; dh++) {
        int hh = h + dh;
        if (hh < 0 || hh >= H) continue;
        #pragma unroll
        for (int dw = -1; dw <= 1; dw++) {
            int ww = w + dw;
            if (ww < 0 || ww >= W) continue;
            s += g_s[n * HW + hh * W + ww];
        }
    }
    g_x2[i] = s;
}

// ---------------------------------------------------------------------------
// Kernel C: main conv + distance epilogue
//   Block: 256 threads -> 8x8 spatial tile x 32 prototypes, one n.
//   Warp = one spatial row (g = tid/32) x 32 prototypes (olane = tid%32).
//   Channels processed in chunks of WCH with smem staging.
// ---------------------------------------------------------------------------
#define WCH 15
#define WSTR 33   // padded proto stride in smem (33 == 1 mod 32 -> conflict-free)

__global__ __launch_bounds__(256, 4)
void conv_dist_kernel(const float* __restrict__ x,
                      const float* __restrict__ wt,
                      float* __restrict__ out) {
    __shared__ float xs[WCH * 100];        // WCH channels x 10x10 halo tile
    __shared__ float ws[WCH * 9 * WSTR];   // WCH channels x 9 taps x 32 protos (padded)

    const int n    = blockIdx.z;
    const int ob   = blockIdx.y;           // proto chunk (8 chunks of 32; last has 1 valid)
    const int tile = blockIdx.x;           // 7x7 = 49 spatial tiles
    const int h0 = (tile / 7) * 8;
    const int w0 = (tile % 7) * 8;

    const int t = threadIdx.x;
    const int olane = t & 31;
    const int g = t >> 5;                  // row within tile, 0..7

    float acc[8];
    #pragma unroll
    for (int j = 0; j < 8; j++) acc[j] = 0.f;

    for (int ch0 = 0; ch0 < C; ch0 += WCH) {
        __syncthreads();

        // ---- stage x halo tiles (WCH * 100 floats) ----
        for (int idx = t; idx < WCH * 100; idx += 256) {
            int cc  = idx / 100;
            int pos = idx % 100;
            int r  = pos / 10, cl = pos % 10;
            int gh = h0 + r - 1, gw = w0 + cl - 1;
            float v = 0.f;
            if (gh >= 0 && gh < H && gw >= 0 && gw < W)
                v = x[(((size_t)n * C + ch0 + cc) * H + gh) * W + gw];
            xs[idx] = v;
        }

        // ---- stage weights, folded with per-channel scalar wc ----
        // idx -> (o = idx/135, dloc = idx%135): coalesced global reads,
        // stride-33 smem writes (conflict-free).
        for (int idx = t; idx < 32 * (WCH * 9); idx += 256) {
            int o    = idx / (WCH * 9);
            int dloc = idx % (WCH * 9);
            int og = ob * 32 + o;
            float v = 0.f;
            if (og < O)
                v = wt[(size_t)og * D + (size_t)ch0 * 9 + dloc];
            int c = ch0 + dloc / 9;
            float wc = (c < SPLIT) ? 0.25f : 0.75f;
            ws[dloc * WSTR + o] = v * wc;
        }

        __syncthreads();

        // ---- compute ----
        #pragma unroll 1
        for (int cc = 0; cc < WCH; ++cc) {
            const float* xr0 = &xs[cc * 100];
            const float* wr0 = &ws[cc * 9 * WSTR];
            #pragma unroll
            for (int kh = 0; kh < 3; kh++) {
                float xr[10];
                #pragma unroll
                for (int k = 0; k < 10; k++)
                    xr[k] = xr0[(g + kh) * 10 + k];   // broadcast within warp
                #pragma unroll
                for (int kw = 0; kw < 3; kw++) {
                    float wv = wr0[(kh * 3 + kw) * WSTR + olane];
                    #pragma unroll
                    for (int j = 0; j < 8; j++)
                        acc[j] = fmaf(xr[j + kw], wv, acc[j]);
                }
            }
        }
    }

    // ---- epilogue: dist = sqrt(max(x2 + p2 - 2*xp, 1e-12)) ----
    int o = ob * 32 + olane;
    if (o < O) {
        float pp = g_p2[o];
        int h = h0 + g;
        #pragma unroll
        for (int j = 0; j < 8; j++) {
            int w = w0 + j;
            float xx = g_x2[n * HW + h * W + w];
            float d2 = xx + pp - 2.f * acc[j];
            out[(((size_t)n * O + o) * H + h) * W + w] = sqrtf(fmaxf(d2, 1e-12f));
        }
    }
}

// ---------------------------------------------------------------------------
extern "C" void kernel_launch(void* const* d_in, const int* in_sizes, int n_in,
                              void* d_out, int out_size) {
    const float* x  = (const float*)d_in[0];   // (32,150,56,56)
    const float* wt = (const float*)d_in[1];   // (225,1350)
    float* out = (float*)d_out;                // (32,225,56,56)

    p2_kernel<<<O, 256>>>(wt);
    chansum_kernel<<<(NB * HW + 255) / 256, 256>>>(x);
    box_kernel<<<(NB * HW + 255) / 256, 256>>>();

    dim3 grid(49, 8, NB);
    conv_dist_kernel<<<grid, 256>>>(x, wt, out);
}

// round 3
// speedup vs baseline: 4.5687x; 4.5687x over previous
#include <cuda_runtime.h>
#include <cuda_bf16.h>
#include <math.h>
#include <stdint.h>

// Problem constants
#define NB  32
#define C   150
#define H   56
#define W   56
#define HW  3136
#define O   225
#define D   1350
#define SPLIT 75

// GEMM geometry
#define KP        1408            // K padded to 44 * 32
#define KCHUNKS   44              // K chunks of 32
#define ROWS_IMG  3200            // HW padded to 25*128
#define MROWS     (NB * ROWS_IMG) // 102400
#define BM 128
#define BN 128
#define BK 32
#define NSTAGE 4
#define ASTR 40                   // smem row stride in halfs (80B, conflict-free)
#define MAT_BYTES (BM * ASTR * 2) // 10240 per A/B tile
#define STAGE_BYTES (2 * MAT_BYTES)
#define SMEM_BYTES (NSTAGE * STAGE_BYTES)  // 81920

// Scratch (__device__ globals; no cudaMalloc allowed)
__device__ float g_p2[O];
__device__ float g_s [NB * HW];
__device__ float g_x2[NB * HW];
__device__ __align__(256) unsigned short A_buf[(size_t)MROWS * KP]; // bf16 im2col
__device__ __align__(256) unsigned short B_pad[256 * KP];           // bf16 w*wc padded

// ---------------------------------------------------------------------------
static __device__ __forceinline__ uint32_t s2u(const void* p) {
    uint32_t a;
    asm("{ .reg .u64 t; cvta.to.shared.u64 t, %1; cvt.u32.u64 %0, t; }"
        : "=r"(a) : "l"(p));
    return a;
}

static __device__ __forceinline__ void cpasync16(uint32_t dst, const void* src) {
    asm volatile("cp.async.cg.shared.global [%0], [%1], 16;"
                 :: "r"(dst), "l"(src));
}

static __device__ __forceinline__ void ldsm4(uint32_t* r, uint32_t addr) {
    asm volatile("ldmatrix.sync.aligned.m8n8.x4.shared.b16 {%0,%1,%2,%3}, [%4];"
                 : "=r"(r[0]), "=r"(r[1]), "=r"(r[2]), "=r"(r[3])
                 : "r"(addr));
}

static __device__ __forceinline__ void mma16816(float* d, const uint32_t* a,
                                                uint32_t b0, uint32_t b1) {
    asm volatile(
        "mma.sync.aligned.m16n8k16.row.col.f32.bf16.bf16.f32 "
        "{%0,%1,%2,%3}, {%4,%5,%6,%7}, {%8,%9}, {%0,%1,%2,%3};"
        : "+f"(d[0]), "+f"(d[1]), "+f"(d[2]), "+f"(d[3])
        : "r"(a[0]), "r"(a[1]), "r"(a[2]), "r"(a[3]), "r"(b0), "r"(b1));
}

static __device__ __forceinline__ unsigned short f2bf(float v) {
    __nv_bfloat16 b = __float2bfloat16(v);
    __nv_bfloat16_raw r = (__nv_bfloat16_raw)b;
    return r.x;
}

// ---------------------------------------------------------------------------
// p2[o] = sum_d wfull[d] * weight[o,d]^2
// ---------------------------------------------------------------------------
__global__ void p2_kernel(const float* __restrict__ wt) {
    int o = blockIdx.x;
    int t = threadIdx.x;
    float s = 0.f;
    for (int d = t; d < D; d += 256) {
        float v = wt[o * D + d];
        float wc = (d < SPLIT * 9) ? 0.25f : 0.75f;
        s += wc * v * v;
    }
    #pragma unroll
    for (int off = 16; off > 0; off >>= 1)
        s += __shfl_down_sync(0xffffffffu, s, off);
    __shared__ float red[8];
    if ((t & 31) == 0) red[t >> 5] = s;
    __syncthreads();
    if (t == 0) {
        float tot = 0.f;
        #pragma unroll
        for (int i = 0; i < 8; i++) tot += red[i];
        g_p2[o] = tot;
    }
}

// ---------------------------------------------------------------------------
// s[n,hw] = sum_c wc * x^2 ; then 3x3 zero-padded box -> g_x2
// ---------------------------------------------------------------------------
__global__ void chansum_kernel(const float* __restrict__ x) {
    int i = blockIdx.x * 256 + threadIdx.x;
    if (i >= NB * HW) return;
    int n = i / HW, hw = i % HW;
    const float* p = x + (size_t)n * C * HW + hw;
    float s = 0.f;
    #pragma unroll 5
    for (int c = 0; c < C; c++) {
        float v = p[(size_t)c * HW];
        float wc = (c < SPLIT) ? 0.25f : 0.75f;
        s += wc * v * v;
    }
    g_s[i] = s;
}

__global__ void box_kernel() {
    int i = blockIdx.x * 256 + threadIdx.x;
    if (i >= NB * HW) return;
    int n = i / HW, hw = i % HW;
    int h = hw / W, w = hw % W;
    float s = 0.f;
    #pragma unroll
    for (int dh = -1; dh <= 1; dh++) {
        int hh = h + dh;
        if (hh < 0 || hh >= H) continue;
        #pragma unroll
        for (int dw = -1; dw <= 1; dw++) {
            int ww = w + dw;
            if (ww < 0 || ww >= W) continue;
            s += g_s[n * HW + hh * W + ww];
        }
    }
    g_x2[i] = s;
}

// ---------------------------------------------------------------------------
// B_pad[o, d] = bf16( weight[o,d] * wc(d) ), zero padded to [256, 1408]
// ---------------------------------------------------------------------------
__global__ void bprep_kernel(const float* __restrict__ wt) {
    int idx = blockIdx.x * 256 + threadIdx.x;
    if (idx >= 256 * (KP / 2)) return;
    int o  = idx / (KP / 2);
    int dp = idx - o * (KP / 2);
    int d0 = dp * 2;
    unsigned short r[2];
    #pragma unroll
    for (int e = 0; e < 2; e++) {
        int d = d0 + e;
        float v = 0.f;
        if (o < O && d < D)
            v = wt[o * D + d] * ((d < SPLIT * 9) ? 0.25f : 0.75f);
        r[e] = f2bf(v);
    }
    *reinterpret_cast<unsigned int*>(&B_pad[o * KP + d0]) =
        *reinterpret_cast<unsigned int*>(r);
}

// ---------------------------------------------------------------------------
// im2col -> A_buf[row, d] bf16.
// ---------------------------------------------------------------------------
__global__ void im2col_kernel(const float* __restrict__ x) {
    int gid = blockIdx.x * 256 + threadIdx.x;
    const int PJ = KP / 8;
    if (gid >= MROWS * PJ) return;
    int row = gid / PJ;
    int j   = gid - row * PJ;
    int d0  = j * 8;
    int n   = row / ROWS_IMG;
    int hw  = row - n * ROWS_IMG;
    bool pv = hw < HW;
    int h = hw / W, w = hw - (hw / W) * W;

    unsigned short res[8];
    #pragma unroll
    for (int e = 0; e < 8; e++) {
        int d = d0 + e;
        float v = 0.f;
        if (pv && d < D) {
            int c  = d / 9;
            int r9 = d - 9 * c;
            int kh = (r9 >= 6) ? 2 : ((r9 >= 3) ? 1 : 0);
            int kw = r9 - 3 * kh;
            int gh = h + kh - 1, gw = w + kw - 1;
            if (gh >= 0 && gh < H && gw >= 0 && gw < W)
                v = x[(((size_t)n * C + c) * H + gh) * W + gw];
        }
        res[e] = f2bf(v);
    }
    *reinterpret_cast<uint4*>(&A_buf[(size_t)row * KP + d0]) =
        *reinterpret_cast<uint4*>(res);
}

// ---------------------------------------------------------------------------
// Main GEMM via mma.sync (HMMA bf16) + fused distance epilogue.
// CTA 128x128, K chunks of 32, 4-stage cp.async pipeline, 8 warps (4M x 2N).
// ---------------------------------------------------------------------------
__global__ __launch_bounds__(256, 2)
void gemm_kernel(float* __restrict__ out) {
    extern __shared__ __align__(128) unsigned char smem[];
    const uint32_t sbase = s2u(smem);
    const int t    = threadIdx.x;
    const int warp = t >> 5, lane = t & 31;
    const int m_base = blockIdx.x * BM;
    const int n_base = blockIdx.y * BN;
    const int warp_m = (warp & 3) * 32;
    const int warp_n = (warp >> 2) * 64;

    // loader coords: 512 16B-chunks per matrix, 2 per thread
    const int lrow = t >> 2, lc16 = t & 3;
    const unsigned short* gA0 = A_buf + (size_t)(m_base + lrow) * KP + lc16 * 8;
    const unsigned short* gA1 = gA0 + (size_t)64 * KP;
    const unsigned short* gB0 = B_pad + (size_t)(n_base + lrow) * KP + lc16 * 8;
    const unsigned short* gB1 = gB0 + (size_t)64 * KP;
    const uint32_t soff = (uint32_t)(lrow * ASTR + lc16 * 8) * 2;  // bytes
    const uint32_t soff2 = soff + 64 * ASTR * 2;

    float acc[2][8][4];
    #pragma unroll
    for (int a = 0; a < 2; a++)
        #pragma unroll
        for (int b = 0; b < 8; b++)
            #pragma unroll
            for (int c = 0; c < 4; c++) acc[a][b][c] = 0.f;

    // ldmatrix address components (byte offsets inside A/B tiles)
    const uint32_t a_row_off = (uint32_t)(lane & 15) * (ASTR * 2);
    const uint32_t a_k_off   = (uint32_t)((lane >> 4) * 8) * 2;
    const uint32_t b_row_off = (uint32_t)((lane & 7) + ((lane >> 4) << 3)) * (ASTR * 2);
    const uint32_t b_k_off   = (uint32_t)(((lane >> 3) & 1) << 3) * 2;

    // prologue: stage chunks 0..2
    #pragma unroll
    for (int s = 0; s < NSTAGE - 1; s++) {
        uint32_t sb = sbase + s * STAGE_BYTES;
        cpasync16(sb + soff,              gA0 + s * BK);
        cpasync16(sb + soff2,             gA1 + s * BK);
        cpasync16(sb + MAT_BYTES + soff,  gB0 + s * BK);
        cpasync16(sb + MAT_BYTES + soff2, gB1 + s * BK);
        asm volatile("cp.async.commit_group;");
    }

    #pragma unroll 1
    for (int i = 0; i < KCHUNKS; i++) {
        if (i + NSTAGE - 1 < KCHUNKS) {
            int s = (i + NSTAGE - 1) & 3;
            int ch = i + NSTAGE - 1;
            uint32_t sb = sbase + s * STAGE_BYTES;
            cpasync16(sb + soff,              gA0 + ch * BK);
            cpasync16(sb + soff2,             gA1 + ch * BK);
            cpasync16(sb + MAT_BYTES + soff,  gB0 + ch * BK);
            cpasync16(sb + MAT_BYTES + soff2, gB1 + ch * BK);
        }
        asm volatile("cp.async.commit_group;");
        asm volatile("cp.async.wait_group 2;");
        __syncthreads();

        const uint32_t ab = sbase + (i & 3) * STAGE_BYTES;
        const uint32_t bb = ab + MAT_BYTES;

        #pragma unroll
        for (int ks = 0; ks < 2; ks++) {
            uint32_t afr[2][4];
            #pragma unroll
            for (int mi = 0; mi < 2; mi++)
                ldsm4(afr[mi], ab + (uint32_t)(warp_m + mi * 16) * (ASTR * 2)
                              + a_row_off + (uint32_t)(ks * 32) + a_k_off);
            #pragma unroll
            for (int nj = 0; nj < 4; nj++) {
                uint32_t bfr[4];
                ldsm4(bfr, bb + (uint32_t)(warp_n + nj * 16) * (ASTR * 2)
                          + b_row_off + (uint32_t)(ks * 32) + b_k_off);
                #pragma unroll
                for (int mi = 0; mi < 2; mi++) {
                    mma16816(acc[mi][nj * 2],     afr[mi], bfr[0], bfr[1]);
                    mma16816(acc[mi][nj * 2 + 1], afr[mi], bfr[2], bfr[3]);
                }
            }
        }
        __syncthreads();
    }

    // -------- epilogue: transpose through smem, fused distance, coalesced --------
    asm volatile("cp.async.wait_group 0;");
    __syncthreads();
    float* cs = reinterpret_cast<float*>(smem);   // [128][132]

    #pragma unroll
    for (int mi = 0; mi < 2; mi++) {
        #pragma unroll
        for (int nj = 0; nj < 8; nj++) {
            int row = warp_m + mi * 16 + (lane >> 2);
            int col = warp_n + nj * 8 + 2 * (lane & 3);
            cs[col * 132 + row]           = acc[mi][nj][0];
            cs[(col + 1) * 132 + row]     = acc[mi][nj][1];
            cs[col * 132 + row + 8]       = acc[mi][nj][2];
            cs[(col + 1) * 132 + row + 8] = acc[mi][nj][3];
        }
    }
    __syncthreads();

    const int img = m_base / ROWS_IMG;
    const int hw0 = m_base % ROWS_IMG;
    #pragma unroll 4
    for (int idx = t; idx < BM * BN; idx += 256) {
        int o_l = idx >> 7, m_l = idx & 127;
        int o = n_base + o_l, hw = hw0 + m_l;
        if (o < O && hw < HW) {
            float d2 = g_x2[img * HW + hw] + g_p2[o] - 2.f * cs[o_l * 132 + m_l];
            out[((size_t)img * O + o) * HW + hw] = sqrtf(fmaxf(d2, 1e-12f));
        }
    }
}

// ---------------------------------------------------------------------------
extern "C" void kernel_launch(void* const* d_in, const int* in_sizes, int n_in,
                              void* d_out, int out_size) {
    const float* x  = (const float*)d_in[0];   // (32,150,56,56)
    const float* wt = (const float*)d_in[1];   // (225,1350)
    float* out = (float*)d_out;                // (32,225,56,56)

    cudaFuncSetAttribute(gemm_kernel,
                         cudaFuncAttributeMaxDynamicSharedMemorySize, SMEM_BYTES);

    p2_kernel<<<O, 256>>>(wt);
    chansum_kernel<<<(NB * HW + 255) / 256, 256>>>(x);
    box_kernel<<<(NB * HW + 255) / 256, 256>>>();
    bprep_kernel<<<(256 * (KP / 2) + 255) / 256, 256>>>(wt);
    {
        int total = MROWS * (KP / 8);
        im2col_kernel<<<(total + 255) / 256, 256>>>(x);
    }
    dim3 grid(MROWS / BM, 2);
    gemm_kernel<<<grid, 256, SMEM_BYTES>>>(out);
}

// round 5
// speedup vs baseline: 5.6233x; 1.2308x over previous
#include <cuda_runtime.h>
#include <cuda_bf16.h>
#include <math.h>
#include <stdint.h>

// Problem constants
#define NB  32
#define C   150
#define H   56
#define W   56
#define HW  3136
#define O   225
#define D   1350
#define SPLIT 75

// Padded image: [NB][58][58][160] bf16, channels-last, zero borders/pad chans
#define PH 58
#define PW 58
#define PC 160

// GEMM geometry (K reordered tap-major: d' = tap*160 + c)
#define KP2 1440                  // 9 taps * 160 padded channels = 45*32
#define KCH 45
#define ROWS_IMG  3200            // HW padded to 25*128
#define MROWS     (NB * ROWS_IMG) // 102400
#define BM 128
#define BN 256
#define BK 32
#define NST 4
#define ASTR 40                   // smem row stride in halfs (80B)
#define A_BYTES (BM * ASTR * 2)   // 10240
#define B_BYTES (BN * ASTR * 2)   // 20480
#define STAGE   (A_BYTES + B_BYTES)
#define SMEM_GEMM (NST * STAGE)   // 122880

// Scratch (__device__ globals; no cudaMalloc allowed)
__device__ float g_p2[O];
__device__ float g_s [NB * HW];
__device__ float g_x2[NB * HW];
__device__ __align__(256) unsigned short x_pad[(size_t)NB * PH * PW * PC];
__device__ __align__(256) unsigned short B_pad[256 * KP2];

// ---------------------------------------------------------------------------
static __device__ __forceinline__ uint32_t s2u(const void* p) {
    uint32_t a;
    asm("{ .reg .u64 t; cvta.to.shared.u64 t, %1; cvt.u32.u64 %0, t; }"
        : "=r"(a) : "l"(p));
    return a;
}

static __device__ __forceinline__ void cpasync16(uint32_t dst, const void* src) {
    asm volatile("cp.async.cg.shared.global [%0], [%1], 16;"
                 :: "r"(dst), "l"(src));
}
static __device__ __forceinline__ void cpasync16z(uint32_t dst, const void* src,
                                                  uint32_t srcsz) {
    asm volatile("cp.async.cg.shared.global [%0], [%1], 16, %2;"
                 :: "r"(dst), "l"(src), "r"(srcsz));
}

static __device__ __forceinline__ void ldsm4(uint32_t* r, uint32_t addr) {
    asm volatile("ldmatrix.sync.aligned.m8n8.x4.shared.b16 {%0,%1,%2,%3}, [%4];"
                 : "=r"(r[0]), "=r"(r[1]), "=r"(r[2]), "=r"(r[3])
                 : "r"(addr));
}

static __device__ __forceinline__ void mma16816(float* d, const uint32_t* a,
                                                uint32_t b0, uint32_t b1) {
    asm volatile(
        "mma.sync.aligned.m16n8k16.row.col.f32.bf16.bf16.f32 "
        "{%0,%1,%2,%3}, {%4,%5,%6,%7}, {%8,%9}, {%0,%1,%2,%3};"
        : "+f"(d[0]), "+f"(d[1]), "+f"(d[2]), "+f"(d[3])
        : "r"(a[0]), "r"(a[1]), "r"(a[2]), "r"(a[3]), "r"(b0), "r"(b1));
}

static __device__ __forceinline__ unsigned short f2bf(float v) {
    __nv_bfloat16 b = __float2bfloat16(v);
    __nv_bfloat16_raw r = (__nv_bfloat16_raw)b;
    return r.x;
}

// ---------------------------------------------------------------------------
// p2[o] = sum_d wfull[d] * weight[o,d]^2
// ---------------------------------------------------------------------------
__global__ void p2_kernel(const float* __restrict__ wt) {
    int o = blockIdx.x;
    int t = threadIdx.x;
    float s = 0.f;
    for (int d = t; d < D; d += 256) {
        float v = wt[o * D + d];
        float wc = (d < SPLIT * 9) ? 0.25f : 0.75f;
        s += wc * v * v;
    }
    #pragma unroll
    for (int off = 16; off > 0; off >>= 1)
        s += __shfl_down_sync(0xffffffffu, s, off);
    __shared__ float red[8];
    if ((t & 31) == 0) red[t >> 5] = s;
    __syncthreads();
    if (t == 0) {
        float tot = 0.f;
        #pragma unroll
        for (int i = 0; i < 8; i++) tot += red[i];
        g_p2[o] = tot;
    }
}

// ---------------------------------------------------------------------------
// s[n,hw] = sum_c wc * x^2 ; then 3x3 zero-padded box -> g_x2
// ---------------------------------------------------------------------------
__global__ void chansum_kernel(const float* __restrict__ x) {
    int i = blockIdx.x * 256 + threadIdx.x;
    if (i >= NB * HW) return;
    int n = i / HW, hw = i % HW;
    const float* p = x + (size_t)n * C * HW + hw;
    float s = 0.f;
    #pragma unroll 5
    for (int c = 0; c < C; c++) {
        float v = p[(size_t)c * HW];
        float wc = (c < SPLIT) ? 0.25f : 0.75f;
        s += wc * v * v;
    }
    g_s[i] = s;
}

__global__ void box_kernel() {
    int i = blockIdx.x * 256 + threadIdx.x;
    if (i >= NB * HW) return;
    int n = i / HW, hw = i % HW;
    int h = hw / W, w = hw % W;
    float s = 0.f;
    #pragma unroll
    for (int dh = -1; dh <= 1; dh++) {
        int hh = h + dh;
        if (hh < 0 || hh >= H) continue;
        #pragma unroll
        for (int dw = -1; dw <= 1; dw++) {
            int ww = w + dw;
            if (ww < 0 || ww >= W) continue;
            s += g_s[n * HW + hh * W + ww];
        }
    }
    g_x2[i] = s;
}

// ---------------------------------------------------------------------------
// B_pad[o, tap*160+c] = bf16( weight[o, c*9+tap] * wc(c) ), zero padded
// ---------------------------------------------------------------------------
__global__ void bprep_kernel(const float* __restrict__ wt) {
    int idx = blockIdx.x * 256 + threadIdx.x;   // 256 * 720 c-pairs
    if (idx >= 256 * (KP2 / 2)) return;
    int o   = idx / (KP2 / 2);
    int rem = idx - o * (KP2 / 2);
    int tap = rem / (PC / 2);
    int cp  = rem - tap * (PC / 2);
    int c0  = cp * 2;
    unsigned short r[2];
    #pragma unroll
    for (int e = 0; e < 2; e++) {
        int c = c0 + e;
        float v = 0.f;
        if (o < O && c < C)
            v = wt[o * D + c * 9 + tap] * ((c < SPLIT) ? 0.25f : 0.75f);
        r[e] = f2bf(v);
    }
    *reinterpret_cast<unsigned int*>(&B_pad[o * KP2 + tap * PC + c0]) =
        *reinterpret_cast<unsigned int*>(r);
}

// ---------------------------------------------------------------------------
// x_pad[n][gh][gw][c] = bf16(x[n,c,gh-1,gw-1]) interior, 0 on borders/pad c.
// One block per (n, gh) row; smem transpose for coalesced access both sides.
// ---------------------------------------------------------------------------
__global__ void xpad_kernel(const float* __restrict__ x) {
    __shared__ float sm[C * W];   // 8400 floats
    int n  = blockIdx.x / PH;
    int gh = blockIdx.x % PH;
    int t  = threadIdx.x;
    bool rowv = (gh >= 1 && gh <= H);
    if (rowv) {
        const float* src = x + ((size_t)n * C * H + (size_t)(gh - 1)) * W;
        for (int idx = t; idx < C * W; idx += 256) {
            int c = idx / W, w = idx - c * W;
            sm[idx] = src[(size_t)c * H * W + w];
        }
    }
    __syncthreads();
    unsigned short* dst = x_pad + ((size_t)n * PH + gh) * PW * PC;
    for (int idx = t; idx < PW * (PC / 2); idx += 256) {
        int gw = idx / (PC / 2);
        int cp = idx - gw * (PC / 2);
        int c  = cp * 2;
        unsigned short r[2] = {0, 0};
        if (rowv && gw >= 1 && gw <= W) {
            if (c < C)     r[0] = f2bf(sm[c * W + gw - 1]);
            if (c + 1 < C) r[1] = f2bf(sm[(c + 1) * W + gw - 1]);
        }
        *reinterpret_cast<unsigned int*>(&dst[gw * PC + c]) =
            *reinterpret_cast<unsigned int*>(r);
    }
}

// ---------------------------------------------------------------------------
// Fused im2col GEMM via mma.sync (HMMA bf16) + distance epilogue.
// CTA: 128 M (one image strip) x 256 N, K = 45 chunks of 32 (tap-major).
// 512 threads = 16 warps (4M x 4N). A tiles stream straight from x_pad.
// ---------------------------------------------------------------------------
__global__ __launch_bounds__(512, 1)
void gemm_kernel(float* __restrict__ out) {
    extern __shared__ __align__(128) unsigned char smem[];
    const uint32_t sbase = s2u(smem);
    const int t    = threadIdx.x;
    const int warp = t >> 5, lane = t & 31;
    const int m_base = blockIdx.x * BM;
    const int img = m_base / ROWS_IMG;
    const int hw0 = m_base % ROWS_IMG;
    const int warp_m = (warp & 3) * 32;
    const int warp_n = (warp >> 2) * 64;

    // ---- A loader coords: thread -> (row r, 16B-quarter q) ----
    const int r = t >> 2, q = t & 3;
    const int hwr = hw0 + r;
    const uint32_t a_size = (hwr < HW) ? 16u : 0u;
    const int hok = (hwr < HW) ? hwr : 0;
    const int hh = hok / W, ww = hok - (hok / W) * W;
    const unsigned short* abase =
        x_pad + (((size_t)img * PH + hh) * PW + ww) * PC + q * 8;
    const uint32_t a_dst = r * (ASTR * 2) + q * 16;

    // ---- B loader coords: row = t>>1 (0..255), 32B half = t&1 ----
    const unsigned short* bb0 = B_pad + (size_t)(t >> 1) * KP2 + (t & 1) * 16;
    const uint32_t b_dst0 = A_BYTES + (t >> 1) * (ASTR * 2) + (t & 1) * 32;

    float acc[2][8][4];
    #pragma unroll
    for (int a = 0; a < 2; a++)
        #pragma unroll
        for (int b = 0; b < 8; b++)
            #pragma unroll
            for (int c = 0; c < 4; c++) acc[a][b][c] = 0.f;

    const uint32_t a_row_off = (uint32_t)(lane & 15) * (ASTR * 2);
    const uint32_t a_k_off   = (uint32_t)((lane >> 4) * 8) * 2;
    const uint32_t b_row_off = (uint32_t)((lane & 7) + ((lane >> 4) << 3)) * (ASTR * 2);
    const uint32_t b_k_off   = (uint32_t)(((lane >> 3) & 1) << 3) * 2;

    // chunk i: tap = i/5 (since 5 chunks of 32 == PC), koff = i*32
    #define LOAD_CHUNK(i_, s_) do {                                          \
        int tap_ = (i_) / 5;                                                 \
        int kh_ = tap_ / 3, kw_ = tap_ - 3 * kh_;                            \
        int aoff_ = (kh_ * PW + kw_) * PC + ((i_) - tap_ * 5) * 32;          \
        uint32_t sb_ = sbase + (uint32_t)(s_) * STAGE;                       \
        cpasync16z(sb_ + a_dst, abase + aoff_, a_size);                      \
        int koff_ = (i_) * 32;                                               \
        cpasync16(sb_ + b_dst0,      bb0 + koff_);                           \
        cpasync16(sb_ + b_dst0 + 16, bb0 + koff_ + 8);                       \
    } while (0)

    #pragma unroll
    for (int s = 0; s < NST - 1; s++) {
        LOAD_CHUNK(s, s);
        asm volatile("cp.async.commit_group;");
    }

    #pragma unroll 1
    for (int i = 0; i < KCH; i++) {
        if (i + NST - 1 < KCH)
            LOAD_CHUNK(i + NST - 1, (i + NST - 1) & (NST - 1));
        asm volatile("cp.async.commit_group;");
        asm volatile("cp.async.wait_group 2;");
        __syncthreads();

        const uint32_t ab = sbase + (uint32_t)(i & (NST - 1)) * STAGE;
        const uint32_t bb = ab + A_BYTES;

        #pragma unroll
        for (int ks = 0; ks < 2; ks++) {
            uint32_t afr[2][4];
            #pragma unroll
            for (int mi = 0; mi < 2; mi++)
                ldsm4(afr[mi], ab + (uint32_t)(warp_m + mi * 16) * (ASTR * 2)
                              + a_row_off + (uint32_t)(ks * 32) + a_k_off);
            #pragma unroll
            for (int nj = 0; nj < 4; nj++) {
                uint32_t bfr[4];
                ldsm4(bfr, bb + (uint32_t)(warp_n + nj * 16) * (ASTR * 2)
                          + b_row_off + (uint32_t)(ks * 32) + b_k_off);
                #pragma unroll
                for (int mi = 0; mi < 2; mi++) {
                    mma16816(acc[mi][nj * 2],     afr[mi], bfr[0], bfr[1]);
                    mma16816(acc[mi][nj * 2 + 1], afr[mi], bfr[2], bfr[3]);
                }
            }
        }
        __syncthreads();
    }
    #undef LOAD_CHUNK

    asm volatile("cp.async.wait_group 0;");
    __syncthreads();

    // -------- epilogue: two 128-o passes through smem, coalesced stores -----
    float* cs = reinterpret_cast<float*>(smem);   // [128 o][132 m]
    #pragma unroll 1
    for (int p = 0; p < 2; p++) {
        if ((warp >> 3) == p) {   // warp_n in [p*128, p*128+128)
            int ob = warp_n - p * 128;
            #pragma unroll
            for (int mi = 0; mi < 2; mi++) {
                #pragma unroll
                for (int nj = 0; nj < 8; nj++) {
                    int row = warp_m + mi * 16 + (lane >> 2);
                    int col = ob + nj * 8 + 2 * (lane & 3);
                    cs[col * 132 + row]           = acc[mi][nj][0];
                    cs[(col + 1) * 132 + row]     = acc[mi][nj][1];
                    cs[col * 132 + row + 8]       = acc[mi][nj][2];
                    cs[(col + 1) * 132 + row + 8] = acc[mi][nj][3];
                }
            }
        }
        __syncthreads();
        #pragma unroll 4
        for (int it = 0; it < 32; it++) {
            int idx = it * 512 + t;
            int o_l = idx >> 7, m_l = idx & 127;
            int o = p * 128 + o_l, hw = hw0 + m_l;
            if (o < O && hw < HW) {
                float d2 = g_x2[img * HW + hw] + g_p2[o] - 2.f * cs[o_l * 132 + m_l];
                out[((size_t)img * O + o) * HW + hw] = sqrtf(fmaxf(d2, 1e-12f));
            }
        }
        __syncthreads();
    }
}

// ---------------------------------------------------------------------------
extern "C" void kernel_launch(void* const* d_in, const int* in_sizes, int n_in,
                              void* d_out, int out_size) {
    const float* x  = (const float*)d_in[0];   // (32,150,56,56)
    const float* wt = (const float*)d_in[1];   // (225,1350)
    float* out = (float*)d_out;                // (32,225,56,56)

    cudaFuncSetAttribute(gemm_kernel,
                         cudaFuncAttributeMaxDynamicSharedMemorySize, SMEM_GEMM);

    p2_kernel<<<O, 256>>>(wt);
    chansum_kernel<<<(NB * HW + 255) / 256, 256>>>(x);
    box_kernel<<<(NB * HW + 255) / 256, 256>>>();
    bprep_kernel<<<(256 * (KP2 / 2) + 255) / 256, 256>>>(wt);
    xpad_kernel<<<NB * PH, 256>>>(x);
    gemm_kernel<<<MROWS / BM, 512, SMEM_GEMM>>>(out);
}

// round 6
// speedup vs baseline: 6.6558x; 1.1836x over previous
#include <cuda_runtime.h>
#include <cuda_bf16.h>
#include <math.h>
#include <stdint.h>

// Problem constants
#define NB  32
#define C   150
#define H   56
#define W   56
#define HW  3136
#define O   225
#define D   1350
#define SPLIT 75

// Padded image: [NB][58][58][160] bf16, channels-last, zero borders/pad chans
#define PH 58
#define PW 58
#define PC 160

// GEMM geometry (K reordered tap-major: d' = tap*160 + c)
#define KP2 1440                  // 9 taps * 160 padded channels = 45*32
#define KCH 45
#define ROWS_IMG  3200            // HW padded to 25*128
#define MROWS     (NB * ROWS_IMG) // 102400
#define BM 128
#define BN 128
#define BK 32
#define NST 4
#define ASTR 40                   // smem row stride in halfs (80B)
#define A_BYTES (BM * ASTR * 2)   // 10240
#define B_BYTES (BN * ASTR * 2)   // 10240
#define STAGE   (A_BYTES + B_BYTES)
#define SMEM_GEMM (NST * STAGE)   // 81920

// Scratch (__device__ globals; no cudaMalloc allowed)
__device__ float g_p2[O];
__device__ float g_s [NB * HW];
__device__ float g_x2[NB * HW];
__device__ __align__(256) unsigned short x_pad[(size_t)NB * PH * PW * PC];
__device__ __align__(256) unsigned short B_pad[256 * KP2];

// ---------------------------------------------------------------------------
static __device__ __forceinline__ uint32_t s2u(const void* p) {
    uint32_t a;
    asm("{ .reg .u64 t; cvta.to.shared.u64 t, %1; cvt.u32.u64 %0, t; }"
        : "=r"(a) : "l"(p));
    return a;
}

static __device__ __forceinline__ void cpasync16(uint32_t dst, const void* src) {
    asm volatile("cp.async.cg.shared.global [%0], [%1], 16;"
                 :: "r"(dst), "l"(src));
}
static __device__ __forceinline__ void cpasync16z(uint32_t dst, const void* src,
                                                  uint32_t srcsz) {
    asm volatile("cp.async.cg.shared.global [%0], [%1], 16, %2;"
                 :: "r"(dst), "l"(src), "r"(srcsz));
}

static __device__ __forceinline__ void ldsm4(uint32_t* r, uint32_t addr) {
    asm volatile("ldmatrix.sync.aligned.m8n8.x4.shared.b16 {%0,%1,%2,%3}, [%4];"
                 : "=r"(r[0]), "=r"(r[1]), "=r"(r[2]), "=r"(r[3])
                 : "r"(addr));
}

static __device__ __forceinline__ void mma16816(float* d, const uint32_t* a,
                                                uint32_t b0, uint32_t b1) {
    asm volatile(
        "mma.sync.aligned.m16n8k16.row.col.f32.bf16.bf16.f32 "
        "{%0,%1,%2,%3}, {%4,%5,%6,%7}, {%8,%9}, {%0,%1,%2,%3};"
        : "+f"(d[0]), "+f"(d[1]), "+f"(d[2]), "+f"(d[3])
        : "r"(a[0]), "r"(a[1]), "r"(a[2]), "r"(a[3]), "r"(b0), "r"(b1));
}

static __device__ __forceinline__ unsigned short f2bf(float v) {
    __nv_bfloat16 b = __float2bfloat16(v);
    __nv_bfloat16_raw r = (__nv_bfloat16_raw)b;
    return r.x;
}

// ---------------------------------------------------------------------------
// p2[o] = sum_d wfull[d] * weight[o,d]^2
// ---------------------------------------------------------------------------
__global__ void p2_kernel(const float* __restrict__ wt) {
    int o = blockIdx.x;
    int t = threadIdx.x;
    float s = 0.f;
    for (int d = t; d < D; d += 256) {
        float v = wt[o * D + d];
        float wc = (d < SPLIT * 9) ? 0.25f : 0.75f;
        s += wc * v * v;
    }
    #pragma unroll
    for (int off = 16; off > 0; off >>= 1)
        s += __shfl_down_sync(0xffffffffu, s, off);
    __shared__ float red[8];
    if ((t & 31) == 0) red[t >> 5] = s;
    __syncthreads();
    if (t == 0) {
        float tot = 0.f;
        #pragma unroll
        for (int i = 0; i < 8; i++) tot += red[i];
        g_p2[o] = tot;
    }
}

// ---------------------------------------------------------------------------
// s[n,hw] = sum_c wc * x^2 ; then 3x3 zero-padded box -> g_x2
// ---------------------------------------------------------------------------
__global__ void chansum_kernel(const float* __restrict__ x) {
    int i = blockIdx.x * 256 + threadIdx.x;
    if (i >= NB * HW) return;
    int n = i / HW, hw = i % HW;
    const float* p = x + (size_t)n * C * HW + hw;
    float s = 0.f;
    #pragma unroll 5
    for (int c = 0; c < C; c++) {
        float v = p[(size_t)c * HW];
        float wc = (c < SPLIT) ? 0.25f : 0.75f;
        s += wc * v * v;
    }
    g_s[i] = s;
}

__global__ void box_kernel() {
    int i = blockIdx.x * 256 + threadIdx.x;
    if (i >= NB * HW) return;
    int n = i / HW, hw = i % HW;
    int h = hw / W, w = hw % W;
    float s = 0.f;
    #pragma unroll
    for (int dh = -1; dh <= 1; dh++) {
        int hh = h + dh;
        if (hh < 0 || hh >= H) continue;
        #pragma unroll
        for (int dw = -1; dw <= 1; dw++) {
            int ww = w + dw;
            if (ww < 0 || ww >= W) continue;
            s += g_s[n * HW + hh * W + ww];
        }
    }
    g_x2[i] = s;
}

// ---------------------------------------------------------------------------
// B_pad[o, tap*160+c] = bf16( weight[o, c*9+tap] * wc(c) ), zero padded
// ---------------------------------------------------------------------------
__global__ void bprep_kernel(const float* __restrict__ wt) {
    int idx = blockIdx.x * 256 + threadIdx.x;   // 256 * 720 c-pairs
    if (idx >= 256 * (KP2 / 2)) return;
    int o   = idx / (KP2 / 2);
    int rem = idx - o * (KP2 / 2);
    int tap = rem / (PC / 2);
    int cp  = rem - tap * (PC / 2);
    int c0  = cp * 2;
    unsigned short r[2];
    #pragma unroll
    for (int e = 0; e < 2; e++) {
        int c = c0 + e;
        float v = 0.f;
        if (o < O && c < C)
            v = wt[o * D + c * 9 + tap] * ((c < SPLIT) ? 0.25f : 0.75f);
        r[e] = f2bf(v);
    }
    *reinterpret_cast<unsigned int*>(&B_pad[o * KP2 + tap * PC + c0]) =
        *reinterpret_cast<unsigned int*>(r);
}

// ---------------------------------------------------------------------------
// x_pad[n][gh][gw][c] = bf16(x[n,c,gh-1,gw-1]) interior, 0 on borders/pad c.
// ---------------------------------------------------------------------------
__global__ void xpad_kernel(const float* __restrict__ x) {
    __shared__ float sm[C * W];   // 8400 floats
    int n  = blockIdx.x / PH;
    int gh = blockIdx.x % PH;
    int t  = threadIdx.x;
    bool rowv = (gh >= 1 && gh <= H);
    if (rowv) {
        const float* src = x + ((size_t)n * C * H + (size_t)(gh - 1)) * W;
        for (int idx = t; idx < C * W; idx += 256) {
            int c = idx / W, w = idx - c * W;
            sm[idx] = src[(size_t)c * H * W + w];
        }
    }
    __syncthreads();
    unsigned short* dst = x_pad + ((size_t)n * PH + gh) * PW * PC;
    for (int idx = t; idx < PW * (PC / 2); idx += 256) {
        int gw = idx / (PC / 2);
        int cp = idx - gw * (PC / 2);
        int c  = cp * 2;
        unsigned short r[2] = {0, 0};
        if (rowv && gw >= 1 && gw <= W) {
            if (c < C)     r[0] = f2bf(sm[c * W + gw - 1]);
            if (c + 1 < C) r[1] = f2bf(sm[(c + 1) * W + gw - 1]);
        }
        *reinterpret_cast<unsigned int*>(&dst[gw * PC + c]) =
            *reinterpret_cast<unsigned int*>(r);
    }
}

// ---------------------------------------------------------------------------
// Fused im2col GEMM via mma.sync (HMMA bf16) + distance epilogue.
// CTA: 128 M x 128 N, 256 threads (8 warps, 4M x 2N, warp tile 32x64),
// K = 45 chunks of 32 tap-major, 4-stage cp.async, ONE barrier per chunk,
// target occupancy 2 CTA/SM.
// ---------------------------------------------------------------------------
__global__ __launch_bounds__(256, 2)
void gemm_kernel(float* __restrict__ out) {
    extern __shared__ __align__(128) unsigned char smem[];
    const uint32_t sbase = s2u(smem);
    const int t    = threadIdx.x;
    const int warp = t >> 5, lane = t & 31;
    const int m_base = blockIdx.x * BM;
    const int n_base = blockIdx.y * BN;
    const int img = m_base / ROWS_IMG;
    const int hw0 = m_base % ROWS_IMG;
    const int warp_m = (warp & 3) * 32;
    const int warp_n = (warp >> 2) * 64;

    // ---- loader coords: row = t>>1 (0..127), 32B half = t&1 ----
    const int r = t >> 1, hb = t & 1;
    const int hwr = hw0 + r;
    const uint32_t a_size = (hwr < HW) ? 16u : 0u;
    const int hok = (hwr < HW) ? hwr : 0;
    const int hh = hok / W, ww = hok - (hok / W) * W;
    const unsigned short* abase =
        x_pad + (((size_t)img * PH + hh) * PW + ww) * PC + hb * 16;
    const uint32_t a_dst = r * (ASTR * 2) + hb * 32;
    const unsigned short* bb0 = B_pad + (size_t)(n_base + r) * KP2 + hb * 16;
    const uint32_t b_dst = A_BYTES + r * (ASTR * 2) + hb * 32;

    float acc[2][8][4];
    #pragma unroll
    for (int a = 0; a < 2; a++)
        #pragma unroll
        for (int b = 0; b < 8; b++)
            #pragma unroll
            for (int c = 0; c < 4; c++) acc[a][b][c] = 0.f;

    const uint32_t a_row_off = (uint32_t)(lane & 15) * (ASTR * 2);
    const uint32_t a_k_off   = (uint32_t)((lane >> 4) * 8) * 2;
    const uint32_t b_row_off = (uint32_t)((lane & 7) + ((lane >> 4) << 3)) * (ASTR * 2);
    const uint32_t b_k_off   = (uint32_t)(((lane >> 3) & 1) << 3) * 2;

    // chunk i: tap = i/5 (5 chunks of 32 == PC), A slice offset in halfs
    #define LOAD_CHUNK(i_, s_) do {                                          \
        int tap_ = (i_) / 5;                                                 \
        int kh_ = tap_ / 3, kw_ = tap_ - 3 * kh_;                            \
        int aoff_ = (kh_ * PW + kw_) * PC + ((i_) - tap_ * 5) * 32;          \
        uint32_t sb_ = sbase + (uint32_t)(s_) * STAGE;                       \
        cpasync16z(sb_ + a_dst,      abase + aoff_,     a_size);             \
        cpasync16z(sb_ + a_dst + 16, abase + aoff_ + 8, a_size);             \
        int koff_ = (i_) * 32;                                               \
        cpasync16(sb_ + b_dst,      bb0 + koff_);                            \
        cpasync16(sb_ + b_dst + 16, bb0 + koff_ + 8);                        \
    } while (0)

    #pragma unroll
    for (int s = 0; s < NST - 1; s++) {
        LOAD_CHUNK(s, s);
        asm volatile("cp.async.commit_group;");
    }

    #pragma unroll 1
    for (int i = 0; i < KCH; i++) {
        // all but the newest NST-2 groups complete => chunk i resident
        asm volatile("cp.async.wait_group %0;" :: "n"(NST - 2));
        __syncthreads();   // also: all warps done computing chunk i-1

        if (i + NST - 1 < KCH)
            LOAD_CHUNK(i + NST - 1, (i + NST - 1) & (NST - 1));
        asm volatile("cp.async.commit_group;");

        const uint32_t ab = sbase + (uint32_t)(i & (NST - 1)) * STAGE;
        const uint32_t bb = ab + A_BYTES;

        #pragma unroll
        for (int ks = 0; ks < 2; ks++) {
            uint32_t afr[2][4];
            #pragma unroll
            for (int mi = 0; mi < 2; mi++)
                ldsm4(afr[mi], ab + (uint32_t)(warp_m + mi * 16) * (ASTR * 2)
                              + a_row_off + (uint32_t)(ks * 32) + a_k_off);
            #pragma unroll
            for (int nj = 0; nj < 4; nj++) {
                uint32_t bfr[4];
                ldsm4(bfr, bb + (uint32_t)(warp_n + nj * 16) * (ASTR * 2)
                          + b_row_off + (uint32_t)(ks * 32) + b_k_off);
                #pragma unroll
                for (int mi = 0; mi < 2; mi++) {
                    mma16816(acc[mi][nj * 2],     afr[mi], bfr[0], bfr[1]);
                    mma16816(acc[mi][nj * 2 + 1], afr[mi], bfr[2], bfr[3]);
                }
            }
        }
    }
    #undef LOAD_CHUNK

    asm volatile("cp.async.wait_group 0;");
    __syncthreads();

    // -------- epilogue: transpose through smem, fused distance, coalesced ----
    float* cs = reinterpret_cast<float*>(smem);   // [128 o][132 m]
    #pragma unroll
    for (int mi = 0; mi < 2; mi++) {
        #pragma unroll
        for (int nj = 0; nj < 8; nj++) {
            int row = warp_m + mi * 16 + (lane >> 2);
            int col = warp_n + nj * 8 + 2 * (lane & 3);
            cs[col * 132 + row]           = acc[mi][nj][0];
            cs[(col + 1) * 132 + row]     = acc[mi][nj][1];
            cs[col * 132 + row + 8]       = acc[mi][nj][2];
            cs[(col + 1) * 132 + row + 8] = acc[mi][nj][3];
        }
    }
    __syncthreads();

    #pragma unroll 4
    for (int it = 0; it < 64; it++) {
        int idx = it * 256 + t;
        int o_l = idx >> 7, m_l = idx & 127;
        int o = n_base + o_l, hw = hw0 + m_l;
        if (o < O && hw < HW) {
            float d2 = g_x2[img * HW + hw] + g_p2[o] - 2.f * cs[o_l * 132 + m_l];
            out[((size_t)img * O + o) * HW + hw] = sqrtf(fmaxf(d2, 1e-12f));
        }
    }
}

// ---------------------------------------------------------------------------
extern "C" void kernel_launch(void* const* d_in, const int* in_sizes, int n_in,
                              void* d_out, int out_size) {
    const float* x  = (const float*)d_in[0];   // (32,150,56,56)
    const float* wt = (const float*)d_in[1];   // (225,1350)
    float* out = (float*)d_out;                // (32,225,56,56)

    cudaFuncSetAttribute(gemm_kernel,
                         cudaFuncAttributeMaxDynamicSharedMemorySize, SMEM_GEMM);

    p2_kernel<<<O, 256>>>(wt);
    chansum_kernel<<<(NB * HW + 255) / 256, 256>>>(x);
    box_kernel<<<(NB * HW + 255) / 256, 256>>>();
    bprep_kernel<<<(256 * (KP2 / 2) + 255) / 256, 256>>>(wt);
    xpad_kernel<<<NB * PH, 256>>>(x);
    dim3 grid(MROWS / BM, 2);
    gemm_kernel<<<grid, 256, SMEM_GEMM>>>(out);
}

// round 7
// speedup vs baseline: 7.1064x; 1.0677x over previous
#include <cuda_runtime.h>
#include <cuda_fp16.h>
#include <math.h>
#include <stdint.h>

// Problem constants
#define NB  32
#define C   150
#define H   56
#define W   56
#define HW  3136
#define O   225
#define D   1350
#define SPLIT 75

// Padded image: [NB][58][58][160] fp16, channels-last, zero borders/pad chans
#define PH 58
#define PW 58
#define PC 160

// GEMM geometry (K reordered tap-major: d' = tap*160 + c)
#define KP2 1440                  // 9 taps * 160 padded channels = 45*32
#define KCH 45
#define ROWS_IMG  3200            // HW padded to 25*128
#define MROWS     (NB * ROWS_IMG) // 102400
#define BM 128
#define BN 128
#define BK 32
#define NST 4
#define ASTR 40                   // smem row stride in halfs (80B)
#define A_BYTES (BM * ASTR * 2)   // 10240
#define B_BYTES (BN * ASTR * 2)   // 10240
#define STAGE   (A_BYTES + B_BYTES)
#define SMEM_GEMM (NST * STAGE)   // 81920

// Scratch (__device__ globals; no cudaMalloc allowed)
__device__ float g_p2[O];
__device__ float g_s [NB * HW];
__device__ float g_x2[NB * HW];
__device__ __align__(256) unsigned short x_pad[(size_t)NB * PH * PW * PC];
__device__ __align__(256) unsigned short B_pad[256 * KP2];

// ---------------------------------------------------------------------------
static __device__ __forceinline__ uint32_t s2u(const void* p) {
    uint32_t a;
    asm("{ .reg .u64 t; cvta.to.shared.u64 t, %1; cvt.u32.u64 %0, t; }"
        : "=r"(a) : "l"(p));
    return a;
}

static __device__ __forceinline__ void cpasync16(uint32_t dst, const void* src) {
    asm volatile("cp.async.cg.shared.global [%0], [%1], 16;"
                 :: "r"(dst), "l"(src));
}
static __device__ __forceinline__ void cpasync16z(uint32_t dst, const void* src,
                                                  uint32_t srcsz) {
    asm volatile("cp.async.cg.shared.global [%0], [%1], 16, %2;"
                 :: "r"(dst), "l"(src), "r"(srcsz));
}

static __device__ __forceinline__ void ldsm4(uint32_t* r, uint32_t addr) {
    asm volatile("ldmatrix.sync.aligned.m8n8.x4.shared.b16 {%0,%1,%2,%3}, [%4];"
                 : "=r"(r[0]), "=r"(r[1]), "=r"(r[2]), "=r"(r[3])
                 : "r"(addr));
}

// fp16 inputs, fp16 accumulate (2x rate vs f32 accum on legacy MMA)
static __device__ __forceinline__ void mma16816h(uint32_t* d, const uint32_t* a,
                                                 uint32_t b0, uint32_t b1) {
    asm volatile(
        "mma.sync.aligned.m16n8k16.row.col.f16.f16.f16.f16 "
        "{%0,%1}, {%2,%3,%4,%5}, {%6,%7}, {%0,%1};"
        : "+r"(d[0]), "+r"(d[1])
        : "r"(a[0]), "r"(a[1]), "r"(a[2]), "r"(a[3]), "r"(b0), "r"(b1));
}

static __device__ __forceinline__ unsigned short f2h(float v) {
    __half h = __float2half(v);
    __half_raw r = (__half_raw)h;
    return r.x;
}

// ---------------------------------------------------------------------------
// p2[o] = sum_d wfull[d] * weight[o,d]^2
// ---------------------------------------------------------------------------
__global__ void p2_kernel(const float* __restrict__ wt) {
    int o = blockIdx.x;
    int t = threadIdx.x;
    float s = 0.f;
    for (int d = t; d < D; d += 256) {
        float v = wt[o * D + d];
        float wc = (d < SPLIT * 9) ? 0.25f : 0.75f;
        s += wc * v * v;
    }
    #pragma unroll
    for (int off = 16; off > 0; off >>= 1)
        s += __shfl_down_sync(0xffffffffu, s, off);
    __shared__ float red[8];
    if ((t & 31) == 0) red[t >> 5] = s;
    __syncthreads();
    if (t == 0) {
        float tot = 0.f;
        #pragma unroll
        for (int i = 0; i < 8; i++) tot += red[i];
        g_p2[o] = tot;
    }
}

// ---------------------------------------------------------------------------
// s[n,hw] = sum_c wc * x^2 ; then 3x3 zero-padded box -> g_x2
// ---------------------------------------------------------------------------
__global__ void chansum_kernel(const float* __restrict__ x) {
    int i = blockIdx.x * 256 + threadIdx.x;
    if (i >= NB * HW) return;
    int n = i / HW, hw = i % HW;
    const float* p = x + (size_t)n * C * HW + hw;
    float s = 0.f;
    #pragma unroll 5
    for (int c = 0; c < C; c++) {
        float v = p[(size_t)c * HW];
        float wc = (c < SPLIT) ? 0.25f : 0.75f;
        s += wc * v * v;
    }
    g_s[i] = s;
}

__global__ void box_kernel() {
    int i = blockIdx.x * 256 + threadIdx.x;
    if (i >= NB * HW) return;
    int n = i / HW, hw = i % HW;
    int h = hw / W, w = hw % W;
    float s = 0.f;
    #pragma unroll
    for (int dh = -1; dh <= 1; dh++) {
        int hh = h + dh;
        if (hh < 0 || hh >= H) continue;
        #pragma unroll
        for (int dw = -1; dw <= 1; dw++) {
            int ww = w + dw;
            if (ww < 0 || ww >= W) continue;
            s += g_s[n * HW + hh * W + ww];
        }
    }
    g_x2[i] = s;
}

// ---------------------------------------------------------------------------
// B_pad[o, tap*160+c] = fp16( weight[o, c*9+tap] * wc(c) ), zero padded
// ---------------------------------------------------------------------------
__global__ void bprep_kernel(const float* __restrict__ wt) {
    int idx = blockIdx.x * 256 + threadIdx.x;   // 256 * 720 c-pairs
    if (idx >= 256 * (KP2 / 2)) return;
    int o   = idx / (KP2 / 2);
    int rem = idx - o * (KP2 / 2);
    int tap = rem / (PC / 2);
    int cp  = rem - tap * (PC / 2);
    int c0  = cp * 2;
    unsigned short r[2];
    #pragma unroll
    for (int e = 0; e < 2; e++) {
        int c = c0 + e;
        float v = 0.f;
        if (o < O && c < C)
            v = wt[o * D + c * 9 + tap] * ((c < SPLIT) ? 0.25f : 0.75f);
        r[e] = f2h(v);
    }
    *reinterpret_cast<unsigned int*>(&B_pad[o * KP2 + tap * PC + c0]) =
        *reinterpret_cast<unsigned int*>(r);
}

// ---------------------------------------------------------------------------
// x_pad[n][gh][gw][c] = fp16(x[n,c,gh-1,gw-1]) interior, 0 on borders/pad c.
// ---------------------------------------------------------------------------
__global__ void xpad_kernel(const float* __restrict__ x) {
    __shared__ float sm[C * W];   // 8400 floats
    int n  = blockIdx.x / PH;
    int gh = blockIdx.x % PH;
    int t  = threadIdx.x;
    bool rowv = (gh >= 1 && gh <= H);
    if (rowv) {
        const float* src = x + ((size_t)n * C * H + (size_t)(gh - 1)) * W;
        for (int idx = t; idx < C * W; idx += 256) {
            int c = idx / W, w = idx - c * W;
            sm[idx] = src[(size_t)c * H * W + w];
        }
    }
    __syncthreads();
    unsigned short* dst = x_pad + ((size_t)n * PH + gh) * PW * PC;
    for (int idx = t; idx < PW * (PC / 2); idx += 256) {
        int gw = idx / (PC / 2);
        int cp = idx - gw * (PC / 2);
        int c  = cp * 2;
        unsigned short r[2] = {0, 0};
        if (rowv && gw >= 1 && gw <= W) {
            if (c < C)     r[0] = f2h(sm[c * W + gw - 1]);
            if (c + 1 < C) r[1] = f2h(sm[(c + 1) * W + gw - 1]);
        }
        *reinterpret_cast<unsigned int*>(&dst[gw * PC + c]) =
            *reinterpret_cast<unsigned int*>(r);
    }
}

// ---------------------------------------------------------------------------
// Fused im2col GEMM via mma.sync fp16 (f16 accum, 2x rate) + distance epilogue.
// CTA: 128 M x 128 N, 256 threads (8 warps, 4M x 2N, warp tile 32x64),
// K = 45 chunks of 32 tap-major, 4-stage cp.async, one barrier per chunk.
// ---------------------------------------------------------------------------
__global__ __launch_bounds__(256, 2)
void gemm_kernel(float* __restrict__ out) {
    extern __shared__ __align__(128) unsigned char smem[];
    const uint32_t sbase = s2u(smem);
    const int t    = threadIdx.x;
    const int warp = t >> 5, lane = t & 31;
    const int m_base = blockIdx.x * BM;
    const int n_base = blockIdx.y * BN;
    const int img = m_base / ROWS_IMG;
    const int hw0 = m_base % ROWS_IMG;
    const int warp_m = (warp & 3) * 32;
    const int warp_n = (warp >> 2) * 64;

    // ---- loader coords: row = t>>1 (0..127), 32B half = t&1 ----
    const int r = t >> 1, hb = t & 1;
    const int hwr = hw0 + r;
    const uint32_t a_size = (hwr < HW) ? 16u : 0u;
    const int hok = (hwr < HW) ? hwr : 0;
    const int hh = hok / W, ww = hok - (hok / W) * W;
    const unsigned short* abase =
        x_pad + (((size_t)img * PH + hh) * PW + ww) * PC + hb * 16;
    const uint32_t a_dst = r * (ASTR * 2) + hb * 32;
    const unsigned short* bb0 = B_pad + (size_t)(n_base + r) * KP2 + hb * 16;
    const uint32_t b_dst = A_BYTES + r * (ASTR * 2) + hb * 32;

    uint32_t acc[2][8][2];
    #pragma unroll
    for (int a = 0; a < 2; a++)
        #pragma unroll
        for (int b = 0; b < 8; b++) { acc[a][b][0] = 0u; acc[a][b][1] = 0u; }

    const uint32_t a_row_off = (uint32_t)(lane & 15) * (ASTR * 2);
    const uint32_t a_k_off   = (uint32_t)((lane >> 4) * 8) * 2;
    const uint32_t b_row_off = (uint32_t)((lane & 7) + ((lane >> 4) << 3)) * (ASTR * 2);
    const uint32_t b_k_off   = (uint32_t)(((lane >> 3) & 1) << 3) * 2;

    // chunk i: tap = i/5 (5 chunks of 32 == PC), A slice offset in halfs
    #define LOAD_CHUNK(i_, s_) do {                                          \
        int tap_ = (i_) / 5;                                                 \
        int kh_ = tap_ / 3, kw_ = tap_ - 3 * kh_;                            \
        int aoff_ = (kh_ * PW + kw_) * PC + ((i_) - tap_ * 5) * 32;          \
        uint32_t sb_ = sbase + (uint32_t)(s_) * STAGE;                       \
        cpasync16z(sb_ + a_dst,      abase + aoff_,     a_size);             \
        cpasync16z(sb_ + a_dst + 16, abase + aoff_ + 8, a_size);             \
        int koff_ = (i_) * 32;                                               \
        cpasync16(sb_ + b_dst,      bb0 + koff_);                            \
        cpasync16(sb_ + b_dst + 16, bb0 + koff_ + 8);                        \
    } while (0)

    #pragma unroll
    for (int s = 0; s < NST - 1; s++) {
        LOAD_CHUNK(s, s);
        asm volatile("cp.async.commit_group;");
    }

    #pragma unroll 1
    for (int i = 0; i < KCH; i++) {
        asm volatile("cp.async.wait_group %0;" :: "n"(NST - 2));
        __syncthreads();

        if (i + NST - 1 < KCH)
            LOAD_CHUNK(i + NST - 1, (i + NST - 1) & (NST - 1));
        asm volatile("cp.async.commit_group;");

        const uint32_t ab = sbase + (uint32_t)(i & (NST - 1)) * STAGE;
        const uint32_t bb = ab + A_BYTES;

        #pragma unroll
        for (int ks = 0; ks < 2; ks++) {
            uint32_t afr[2][4];
            #pragma unroll
            for (int mi = 0; mi < 2; mi++)
                ldsm4(afr[mi], ab + (uint32_t)(warp_m + mi * 16) * (ASTR * 2)
                              + a_row_off + (uint32_t)(ks * 32) + a_k_off);
            #pragma unroll
            for (int nj = 0; nj < 4; nj++) {
                uint32_t bfr[4];
                ldsm4(bfr, bb + (uint32_t)(warp_n + nj * 16) * (ASTR * 2)
                          + b_row_off + (uint32_t)(ks * 32) + b_k_off);
                #pragma unroll
                for (int mi = 0; mi < 2; mi++) {
                    mma16816h(acc[mi][nj * 2],     afr[mi], bfr[0], bfr[1]);
                    mma16816h(acc[mi][nj * 2 + 1], afr[mi], bfr[2], bfr[3]);
                }
            }
        }
    }
    #undef LOAD_CHUNK

    asm volatile("cp.async.wait_group 0;");
    __syncthreads();

    // -------- epilogue: transpose through smem, fused distance, coalesced ----
    float* cs = reinterpret_cast<float*>(smem);   // [128 o][132 m]
    #pragma unroll
    for (int mi = 0; mi < 2; mi++) {
        #pragma unroll
        for (int nj = 0; nj < 8; nj++) {
            int row = warp_m + mi * 16 + (lane >> 2);
            int col = warp_n + nj * 8 + 2 * (lane & 3);
            float2 f01 = __half22float2(
                *reinterpret_cast<const __half2*>(&acc[mi][nj][0]));
            float2 f23 = __half22float2(
                *reinterpret_cast<const __half2*>(&acc[mi][nj][1]));
            cs[col * 132 + row]           = f01.x;
            cs[(col + 1) * 132 + row]     = f01.y;
            cs[col * 132 + row + 8]       = f23.x;
            cs[(col + 1) * 132 + row + 8] = f23.y;
        }
    }
    __syncthreads();

    #pragma unroll 4
    for (int it = 0; it < 64; it++) {
        int idx = it * 256 + t;
        int o_l = idx >> 7, m_l = idx & 127;
        int o = n_base + o_l, hw = hw0 + m_l;
        if (o < O && hw < HW) {
            float d2 = g_x2[img * HW + hw] + g_p2[o] - 2.f * cs[o_l * 132 + m_l];
            out[((size_t)img * O + o) * HW + hw] = sqrtf(fmaxf(d2, 1e-12f));
        }
    }
}

// ---------------------------------------------------------------------------
extern "C" void kernel_launch(void* const* d_in, const int* in_sizes, int n_in,
                              void* d_out, int out_size) {
    const float* x  = (const float*)d_in[0];   // (32,150,56,56)
    const float* wt = (const float*)d_in[1];   // (225,1350)
    float* out = (float*)d_out;                // (32,225,56,56)

    cudaFuncSetAttribute(gemm_kernel,
                         cudaFuncAttributeMaxDynamicSharedMemorySize, SMEM_GEMM);

    p2_kernel<<<O, 256>>>(wt);
    chansum_kernel<<<(NB * HW + 255) / 256, 256>>>(x);
    box_kernel<<<(NB * HW + 255) / 256, 256>>>();
    bprep_kernel<<<(256 * (KP2 / 2) + 255) / 256, 256>>>(wt);
    xpad_kernel<<<NB * PH, 256>>>(x);
    dim3 grid(MROWS / BM, 2);
    gemm_kernel<<<grid, 256, SMEM_GEMM>>>(out);
}